// round 2
// baseline (speedup 1.0000x reference)
#include <cuda_runtime.h>

#define B_    64
#define S_    512
#define H_    128
#define NH_   4
#define NHH_  512
#define QSCALE 0.08838834764831845f   /* 1/sqrt(128) */
#define NEG_INF_ -1e9f

// ---------------- scratch (allocation-free: __device__ globals) --------------
__device__ float g_Q[(size_t)B_ * NH_ * S_ * H_];   // (b,h,s,d), pre-scaled by 1/sqrt(H)
__device__ float g_K[(size_t)B_ * NH_ * S_ * H_];   // (b,h,s,d)
__device__ float g_V[(size_t)B_ * NH_ * S_ * H_];   // (b,h,s,d)
__device__ float g_ctx[(size_t)B_ * S_ * NHH_];     // (b,s, h*H+d)

// ---------------- swizzled float4 shared-memory tiles ------------------------
// Tile = rows x (nsl slots of float4). Physical slot = slot ^ (row & (nsl-1)).
// Makes both row-internal and row-spread LDS.128 patterns hit the 256B/2-phase
// structural minimum (a plain pitch of 128 floats would be 16-way conflicted).
__device__ __forceinline__ float4 ld4sw(const float* b, int row, int slot, int nsl) {
    int ph = slot ^ (row & (nsl - 1));
    return *reinterpret_cast<const float4*>(b + ((row * nsl + ph) << 2));
}
__device__ __forceinline__ void st4sw(float* b, int row, int slot, int nsl, float4 v) {
    int ph = slot ^ (row & (nsl - 1));
    *reinterpret_cast<float4*>(b + ((row * nsl + ph) << 2)) = v;
}

// =============================================================================
// Kernel 1: fused QKV projection.  X(32768x128) @ W(128x512) -> (b,h,s,d)
// grid = (8 n-tiles, 512 m-tiles, 3 {Q,K,V}), 256 threads, 64x64 tile, 4x4/thr
// =============================================================================
__global__ void __launch_bounds__(256) qkv_kernel(
    const float* __restrict__ enc, const float* __restrict__ Wq,
    const float* __restrict__ Wk,  const float* __restrict__ Wv)
{
    __shared__ float As[64 * 64];   // 64 m-rows x 16 slots (k)
    __shared__ float Bs[64 * 64];   // 64 k-rows x 16 slots (n)
    const int tid = threadIdx.x, tx = tid & 15, ty = tid >> 4;
    const int n0 = blockIdx.x * 64, m0 = blockIdx.y * 64, z = blockIdx.z;
    const float* W = (z == 0) ? Wq : (z == 1) ? Wk : Wv;

    float acc[4][4];
#pragma unroll
    for (int i = 0; i < 4; i++)
#pragma unroll
        for (int j = 0; j < 4; j++) acc[i][j] = 0.0f;

    for (int kc = 0; kc < H_; kc += 64) {
        if (kc) __syncthreads();
#pragma unroll
        for (int t = 0; t < 4; t++) {
            int idx = tid + t * 256;
            int r = idx >> 4, sl = idx & 15;
            float4 a = *reinterpret_cast<const float4*>(&enc[(size_t)(m0 + r) * H_ + kc + sl * 4]);
            st4sw(As, r, sl, 16, a);
            float4 b = *reinterpret_cast<const float4*>(&W[(size_t)(kc + r) * NHH_ + n0 + sl * 4]);
            st4sw(Bs, r, sl, 16, b);
        }
        __syncthreads();
#pragma unroll
        for (int s = 0; s < 16; s++) {
            float4 av[4], bv[4];
#pragma unroll
            for (int i = 0; i < 4; i++) av[i] = ld4sw(As, 4 * ty + i, s, 16);
#pragma unroll
            for (int t = 0; t < 4; t++) bv[t] = ld4sw(Bs, 4 * s + t, tx, 16);
#pragma unroll
            for (int i = 0; i < 4; i++) {
                const float* ai = reinterpret_cast<const float*>(&av[i]);
#pragma unroll
                for (int t = 0; t < 4; t++) {
                    const float* bt = reinterpret_cast<const float*>(&bv[t]);
                    float a = ai[t];
                    acc[i][0] += a * bt[0]; acc[i][1] += a * bt[1];
                    acc[i][2] += a * bt[2]; acc[i][3] += a * bt[3];
                }
            }
        }
    }

    const float scl = (z == 0) ? QSCALE : 1.0f;
    float* dst = (z == 0) ? g_Q : (z == 1) ? g_K : g_V;
    const int n = n0 + 4 * tx;
    const int h = n >> 7, d = n & 127;
#pragma unroll
    for (int i = 0; i < 4; i++) {
        int m = m0 + 4 * ty + i;
        int bb = m >> 9, s = m & 511;
        float4 o = make_float4(acc[i][0] * scl, acc[i][1] * scl,
                               acc[i][2] * scl, acc[i][3] * scl);
        *reinterpret_cast<float4*>(&dst[((size_t)(bb * NH_ + h) * S_ + s) * H_ + d]) = o;
    }
}

// =============================================================================
// Kernel 2: flash attention, fp32, masked, online softmax.
// grid = (8 q-tiles, NH, B), 256 threads; q-tile 64, k-tile 64, head_dim 128.
// smem (dynamic, 112 KB): Qs/Ks/Vs 64x128 + Ps 64x64.
// Per-thread: scores 4x4 (rows 4ty+i, cols 4tx+j); O 4x8 (cols 4tx & 64+4tx).
// Row stats reduced over the 16-lane tx-group via shfl.xor (groups are
// 16-aligned within warps since tid = ty*16+tx).
// =============================================================================
__global__ void __launch_bounds__(256, 2) attn_kernel(const int* __restrict__ mask)
{
    extern __shared__ float sm[];
    float* Qs = sm;                 // 64 x 32 slots
    float* Ks = sm + 8192;          // 64 x 32 slots
    float* Vs = sm + 16384;         // 64 x 32 slots
    float* Ps = sm + 24576;         // 64 x 64 plain floats

    const int tid = threadIdx.x, tx = tid & 15, ty = tid >> 4;
    const int q0 = blockIdx.x * 64;
    const int h = blockIdx.y, bb = blockIdx.z;
    const size_t bh = (size_t)(bb * NH_ + h);
    const float* Qg = g_Q + bh * S_ * H_;
    const float* Kg = g_K + bh * S_ * H_;
    const float* Vg = g_V + bh * S_ * H_;

#pragma unroll
    for (int t = 0; t < 8; t++) {
        int idx = tid + t * 256;
        int r = idx >> 5, sl = idx & 31;
        st4sw(Qs, r, sl, 32,
              *reinterpret_cast<const float4*>(&Qg[(size_t)(q0 + r) * H_ + sl * 4]));
    }

    float O[4][8];
    float mI[4], lI[4];
#pragma unroll
    for (int i = 0; i < 4; i++) {
        mI[i] = -1e30f; lI[i] = 0.0f;
#pragma unroll
        for (int j = 0; j < 8; j++) O[i][j] = 0.0f;
    }

    for (int kt = 0; kt < 8; kt++) {
        __syncthreads();                       // prev iter done with Ks/Vs/Ps
        const int k0 = kt * 64;
#pragma unroll
        for (int t = 0; t < 8; t++) {
            int idx = tid + t * 256;
            int r = idx >> 5, sl = idx & 31;
            st4sw(Ks, r, sl, 32,
                  *reinterpret_cast<const float4*>(&Kg[(size_t)(k0 + r) * H_ + sl * 4]));
            st4sw(Vs, r, sl, 32,
                  *reinterpret_cast<const float4*>(&Vg[(size_t)(k0 + r) * H_ + sl * 4]));
        }
        __syncthreads();

        // ---- S = Q K^T (Q pre-scaled by 1/sqrt(H)) ----
        float sc4[4][4];
#pragma unroll
        for (int i = 0; i < 4; i++)
#pragma unroll
            for (int j = 0; j < 4; j++) sc4[i][j] = 0.0f;
#pragma unroll
        for (int s = 0; s < 32; s++) {
            float4 qa[4], kb[4];
#pragma unroll
            for (int i = 0; i < 4; i++) qa[i] = ld4sw(Qs, 4 * ty + i, s, 32);
#pragma unroll
            for (int j = 0; j < 4; j++) kb[j] = ld4sw(Ks, 4 * tx + j, s, 32);
#pragma unroll
            for (int i = 0; i < 4; i++)
#pragma unroll
                for (int j = 0; j < 4; j++)
                    sc4[i][j] += qa[i].x * kb[j].x + qa[i].y * kb[j].y +
                                 qa[i].z * kb[j].z + qa[i].w * kb[j].w;
        }

        // ---- mask + online softmax ----
#pragma unroll
        for (int i = 0; i < 4; i++) {
            int q = q0 + 4 * ty + i;
            int4 mk = *reinterpret_cast<const int4*>(
                &mask[((size_t)bb * S_ + q) * S_ + k0 + 4 * tx]);
            if (mk.x == 0) sc4[i][0] = NEG_INF_;
            if (mk.y == 0) sc4[i][1] = NEG_INF_;
            if (mk.z == 0) sc4[i][2] = NEG_INF_;
            if (mk.w == 0) sc4[i][3] = NEG_INF_;

            float mx = fmaxf(fmaxf(sc4[i][0], sc4[i][1]), fmaxf(sc4[i][2], sc4[i][3]));
#pragma unroll
            for (int o = 8; o > 0; o >>= 1)
                mx = fmaxf(mx, __shfl_xor_sync(0xffffffffu, mx, o));
            float mn = fmaxf(mI[i], mx);
            float alpha = __expf(mI[i] - mn);
            mI[i] = mn;

            float p0 = __expf(sc4[i][0] - mn);
            float p1 = __expf(sc4[i][1] - mn);
            float p2 = __expf(sc4[i][2] - mn);
            float p3 = __expf(sc4[i][3] - mn);
            *reinterpret_cast<float4*>(&Ps[(4 * ty + i) * 64 + 4 * tx]) =
                make_float4(p0, p1, p2, p3);

            float ps = p0 + p1 + p2 + p3;
#pragma unroll
            for (int o = 8; o > 0; o >>= 1)
                ps += __shfl_xor_sync(0xffffffffu, ps, o);
            lI[i] = lI[i] * alpha + ps;
#pragma unroll
            for (int j = 0; j < 8; j++) O[i][j] *= alpha;
        }
        __syncthreads();                       // Ps visible to all

        // ---- O += P @ V ----
#pragma unroll 4
        for (int c = 0; c < 64; c++) {
            float4 va = ld4sw(Vs, c, tx, 32);        // d = 4tx..4tx+3
            float4 vb = ld4sw(Vs, c, tx + 16, 32);   // d = 64+4tx..
#pragma unroll
            for (int i = 0; i < 4; i++) {
                float p = Ps[(4 * ty + i) * 64 + c];
                O[i][0] += p * va.x; O[i][1] += p * va.y;
                O[i][2] += p * va.z; O[i][3] += p * va.w;
                O[i][4] += p * vb.x; O[i][5] += p * vb.y;
                O[i][6] += p * vb.z; O[i][7] += p * vb.w;
            }
        }
    }

    // ---- normalize + write ctx (b, s, h*H+d) ----
#pragma unroll
    for (int i = 0; i < 4; i++) {
        float inv = 1.0f / lI[i];
        int q = q0 + 4 * ty + i;
        float* dst = g_ctx + ((size_t)bb * S_ + q) * NHH_ + h * H_;
        *reinterpret_cast<float4*>(&dst[4 * tx]) =
            make_float4(O[i][0] * inv, O[i][1] * inv, O[i][2] * inv, O[i][3] * inv);
        *reinterpret_cast<float4*>(&dst[64 + 4 * tx]) =
            make_float4(O[i][4] * inv, O[i][5] * inv, O[i][6] * inv, O[i][7] * inv);
    }
}

// =============================================================================
// Kernel 3: out = ctx @ Wo + enc, then LayerNorm(last dim).
// grid = 512 m-tiles of 64 rows; full N=128 per block; 4x8 per thread.
// =============================================================================
__global__ void __launch_bounds__(256) out_kernel(
    const float* __restrict__ enc, const float* __restrict__ Wo,
    const float* __restrict__ gamma, const float* __restrict__ beta,
    float* __restrict__ out)
{
    __shared__ float As[64 * 32];    // 64 m-rows x 8 slots (k)
    __shared__ float Bs[32 * 128];   // 32 k-rows x 32 slots (n)
    const int tid = threadIdx.x, tx = tid & 15, ty = tid >> 4;
    const int m0 = blockIdx.x * 64;

    float acc[4][8];
#pragma unroll
    for (int i = 0; i < 4; i++)
#pragma unroll
        for (int j = 0; j < 8; j++) acc[i][j] = 0.0f;

    for (int kc = 0; kc < NHH_; kc += 32) {
        if (kc) __syncthreads();
#pragma unroll
        for (int t = 0; t < 2; t++) {
            int idx = tid + t * 256;
            int r = idx >> 3, sl = idx & 7;
            st4sw(As, r, sl, 8,
                  *reinterpret_cast<const float4*>(&g_ctx[(size_t)(m0 + r) * NHH_ + kc + sl * 4]));
        }
#pragma unroll
        for (int t = 0; t < 4; t++) {
            int idx = tid + t * 256;
            int r = idx >> 5, sl = idx & 31;
            st4sw(Bs, r, sl, 32,
                  *reinterpret_cast<const float4*>(&Wo[(size_t)(kc + r) * H_ + sl * 4]));
        }
        __syncthreads();
#pragma unroll
        for (int s = 0; s < 8; s++) {
            float4 av[4];
#pragma unroll
            for (int i = 0; i < 4; i++) av[i] = ld4sw(As, 4 * ty + i, s, 8);
#pragma unroll
            for (int t = 0; t < 4; t++) {
                int k = 4 * s + t;
                float4 b1 = ld4sw(Bs, k, tx, 32);
                float4 b2 = ld4sw(Bs, k, tx + 16, 32);
#pragma unroll
                for (int i = 0; i < 4; i++) {
                    float a = reinterpret_cast<const float*>(&av[i])[t];
                    acc[i][0] += a * b1.x; acc[i][1] += a * b1.y;
                    acc[i][2] += a * b1.z; acc[i][3] += a * b1.w;
                    acc[i][4] += a * b2.x; acc[i][5] += a * b2.y;
                    acc[i][6] += a * b2.z; acc[i][7] += a * b2.w;
                }
            }
        }
    }

    float4 g1  = *reinterpret_cast<const float4*>(&gamma[4 * tx]);
    float4 g2  = *reinterpret_cast<const float4*>(&gamma[64 + 4 * tx]);
    float4 be1 = *reinterpret_cast<const float4*>(&beta[4 * tx]);
    float4 be2 = *reinterpret_cast<const float4*>(&beta[64 + 4 * tx]);

#pragma unroll
    for (int i = 0; i < 4; i++) {
        int m = m0 + 4 * ty + i;
        float4 e1 = *reinterpret_cast<const float4*>(&enc[(size_t)m * H_ + 4 * tx]);
        float4 e2 = *reinterpret_cast<const float4*>(&enc[(size_t)m * H_ + 64 + 4 * tx]);
        float x[8];
        x[0] = acc[i][0] + e1.x; x[1] = acc[i][1] + e1.y;
        x[2] = acc[i][2] + e1.z; x[3] = acc[i][3] + e1.w;
        x[4] = acc[i][4] + e2.x; x[5] = acc[i][5] + e2.y;
        x[6] = acc[i][6] + e2.z; x[7] = acc[i][7] + e2.w;

        float sm_ = 0.0f, sq = 0.0f;
#pragma unroll
        for (int j = 0; j < 8; j++) { sm_ += x[j]; sq += x[j] * x[j]; }
#pragma unroll
        for (int o = 8; o > 0; o >>= 1) {
            sm_ += __shfl_xor_sync(0xffffffffu, sm_, o);
            sq  += __shfl_xor_sync(0xffffffffu, sq,  o);
        }
        float mean = sm_ * (1.0f / 128.0f);
        float var  = sq * (1.0f / 128.0f) - mean * mean;
        float rstd = rsqrtf(var + 1e-6f);

        float4 y1 = make_float4((x[0] - mean) * rstd * g1.x + be1.x,
                                (x[1] - mean) * rstd * g1.y + be1.y,
                                (x[2] - mean) * rstd * g1.z + be1.z,
                                (x[3] - mean) * rstd * g1.w + be1.w);
        float4 y2 = make_float4((x[4] - mean) * rstd * g2.x + be2.x,
                                (x[5] - mean) * rstd * g2.y + be2.y,
                                (x[6] - mean) * rstd * g2.z + be2.z,
                                (x[7] - mean) * rstd * g2.w + be2.w);
        *reinterpret_cast<float4*>(&out[(size_t)m * H_ + 4 * tx]) = y1;
        *reinterpret_cast<float4*>(&out[(size_t)m * H_ + 64 + 4 * tx]) = y2;
    }
}

// =============================================================================
extern "C" void kernel_launch(void* const* d_in, const int* in_sizes, int n_in,
                              void* d_out, int out_size)
{
    const float* enc   = (const float*)d_in[0];
    const int*   mask  = (const int*)  d_in[1];
    const float* Wq    = (const float*)d_in[2];
    const float* Wk    = (const float*)d_in[3];
    const float* Wv    = (const float*)d_in[4];
    const float* Wo    = (const float*)d_in[5];
    const float* gamma = (const float*)d_in[6];
    const float* beta  = (const float*)d_in[7];
    float* out = (float*)d_out;

    dim3 g1(NHH_ / 64, (B_ * S_) / 64, 3);
    qkv_kernel<<<g1, 256>>>(enc, Wq, Wk, Wv);

    const int smem2 = (3 * 64 * H_ + 64 * 64) * (int)sizeof(float);  // 114688 B
    cudaFuncSetAttribute(attn_kernel, cudaFuncAttributeMaxDynamicSharedMemorySize, smem2);
    dim3 g2(S_ / 64, NH_, B_);
    attn_kernel<<<g2, 256, smem2>>>(mask);

    out_kernel<<<(B_ * S_) / 64, 256>>>(enc, Wo, gamma, beta, out);
}

// round 3
// speedup vs baseline: 3.0727x; 3.0727x over previous
#include <cuda_runtime.h>

#define B_    64
#define S_    512
#define H_    128
#define NH_   4
#define NHH_  512
#define QSCALE 0.08838834764831845f   /* 1/sqrt(128) */
#define NEG_INF_ -1e9f

// ---------------- scratch (allocation-free: __device__ globals) --------------
__device__ float g_Q[(size_t)B_ * NH_ * S_ * H_];   // (b,h,s,d), tf32-rounded, pre-scaled
__device__ float g_K[(size_t)B_ * NH_ * S_ * H_];   // (b,h,s,d), tf32-rounded
__device__ float g_V[(size_t)B_ * NH_ * S_ * H_];   // (b,h,s,d), tf32-rounded
__device__ float g_ctx[(size_t)B_ * S_ * NHH_];     // (b,s, h*H+d), fp32

// ---------------- tf32 helpers ----------------------------------------------
__device__ __forceinline__ float tf32r(float x) {   // round-to-nearest tf32, as float bits
    unsigned u;
    asm("cvt.rna.tf32.f32 %0, %1;" : "=r"(u) : "f"(x));
    return __uint_as_float(u);
}

__device__ __forceinline__ void mma_tf32(float c[4],
                                         unsigned a0, unsigned a1, unsigned a2, unsigned a3,
                                         unsigned b0, unsigned b1) {
    asm volatile(
        "mma.sync.aligned.m16n8k8.row.col.f32.tf32.tf32.f32 "
        "{%0,%1,%2,%3}, {%4,%5,%6,%7}, {%8,%9}, {%0,%1,%2,%3};"
        : "+f"(c[0]), "+f"(c[1]), "+f"(c[2]), "+f"(c[3])
        : "r"(a0), "r"(a1), "r"(a2), "r"(a3), "r"(b0), "r"(b1));
}

// =============================================================================
// Kernel 1: fused QKV projection via tf32 MMA.
// X(32768x128) @ W(128x512) -> (b,h,s,d), rounded to tf32 (RN) on store.
// grid = (8 n-tiles, 512 m-tiles, 3 {Q,K,V}), 256 threads (8 warps: 4m x 2n),
// tile 64m x 64n x 128k (single k chunk).
// smem: Es 64x(pitch 132), Ws 128x(pitch 72) -> 70656 B dynamic.
// Fragment LDS bank patterns: A bank=(4*gid+8s+tig) distinct; B bank=(8*tig+8*nt+gid) distinct.
// =============================================================================
__global__ void __launch_bounds__(256, 2) qkv_kernel(
    const float* __restrict__ enc, const float* __restrict__ Wq,
    const float* __restrict__ Wk,  const float* __restrict__ Wv)
{
    extern __shared__ float sm[];
    float* Es = sm;             // 64 x 132
    float* Ws = sm + 64 * 132;  // 128 x 72

    const int tid  = threadIdx.x;
    const int lane = tid & 31, wid = tid >> 5;
    const int gid  = lane >> 2, tig = lane & 3;
    const int mw   = wid & 3,  nw  = wid >> 2;
    const int n0 = blockIdx.x * 64, m0 = blockIdx.y * 64, z = blockIdx.z;
    const float* W = (z == 0) ? Wq : (z == 1) ? Wk : Wv;

    // fill enc tile (64x128) and W tile (128x64), rounding inputs to tf32 RN
#pragma unroll
    for (int t = 0; t < 8; t++) {
        int idx = tid + t * 256;
        int r = idx >> 5, sl = idx & 31;
        float4 a = *reinterpret_cast<const float4*>(&enc[(size_t)(m0 + r) * H_ + sl * 4]);
        float* d = &Es[r * 132 + sl * 4];
        d[0] = tf32r(a.x); d[1] = tf32r(a.y); d[2] = tf32r(a.z); d[3] = tf32r(a.w);
    }
#pragma unroll
    for (int t = 0; t < 8; t++) {
        int idx = tid + t * 256;
        int r = idx >> 4, sl = idx & 15;
        float4 b = *reinterpret_cast<const float4*>(&W[(size_t)r * NHH_ + n0 + sl * 4]);
        float* d = &Ws[r * 72 + sl * 4];
        d[0] = tf32r(b.x); d[1] = tf32r(b.y); d[2] = tf32r(b.z); d[3] = tf32r(b.w);
    }
    __syncthreads();

    float c[4][4];
#pragma unroll
    for (int nt = 0; nt < 4; nt++)
#pragma unroll
        for (int j = 0; j < 4; j++) c[nt][j] = 0.0f;

    const unsigned* Eu = reinterpret_cast<const unsigned*>(Es);
    const unsigned* Wu = reinterpret_cast<const unsigned*>(Ws);
    const int r0 = mw * 16 + gid;

#pragma unroll
    for (int s = 0; s < 16; s++) {
        unsigned a0 = Eu[r0 * 132 + 8 * s + tig];
        unsigned a1 = Eu[(r0 + 8) * 132 + 8 * s + tig];
        unsigned a2 = Eu[r0 * 132 + 8 * s + tig + 4];
        unsigned a3 = Eu[(r0 + 8) * 132 + 8 * s + tig + 4];
#pragma unroll
        for (int nt = 0; nt < 4; nt++) {
            int nn = nw * 32 + nt * 8 + gid;
            unsigned b0 = Wu[(8 * s + tig) * 72 + nn];
            unsigned b1 = Wu[(8 * s + tig + 4) * 72 + nn];
            mma_tf32(c[nt], a0, a1, a2, a3, b0, b1);
        }
    }

    // epilogue: scale (Q only), round RN to tf32, scatter to (b,h,s,d)
    const float scl = (z == 0) ? QSCALE : 1.0f;
    float* dst = (z == 0) ? g_Q : (z == 1) ? g_K : g_V;
    const int m  = m0 + r0;
    const int bb = m >> 9, srow = m & 511;
    const int bb2 = (m + 8) >> 9, srow2 = (m + 8) & 511;
#pragma unroll
    for (int nt = 0; nt < 4; nt++) {
        int n = n0 + nw * 32 + nt * 8 + 2 * tig;
        int h = n >> 7, d = n & 127;
        float2 v0 = make_float2(tf32r(c[nt][0] * scl), tf32r(c[nt][1] * scl));
        float2 v1 = make_float2(tf32r(c[nt][2] * scl), tf32r(c[nt][3] * scl));
        *reinterpret_cast<float2*>(
            &dst[((size_t)(bb  * NH_ + h) * S_ + srow ) * H_ + d]) = v0;
        *reinterpret_cast<float2*>(
            &dst[((size_t)(bb2 * NH_ + h) * S_ + srow2) * H_ + d]) = v1;
    }
}

// =============================================================================
// Kernel 2: flash attention via tf32 MMA, masked, online softmax.
// grid = (8 q-tiles, NH, B), 256 threads (8 warps: 4m x 2n).
// q-tile 64, k-tile 64, D=128.
// smem (103424 B dynamic): Qs 64x132, Ks 64x132 (Ps 64x68 ALIASED on top of Ks
// — K tile is dead after QK^T each iter), Vs 64x136, rmax/rsum [2][64].
// 2 CTAs/SM (<=128 regs via launch_bounds).
// =============================================================================
__global__ void __launch_bounds__(256, 2) attn_kernel(const int* __restrict__ mask)
{
    extern __shared__ float sm[];
    float* Qs   = sm;                    // 64 x 132 = 8448
    float* Ks   = sm + 8448;             // 64 x 132 = 8448
    float* Ps   = Ks;                    // 64 x 68 (alias)
    float* Vs   = sm + 16896;            // 64 x 136 = 8704
    float* rmax = sm + 25600;            // [2][64]
    float* rsum = sm + 25728;            // [2][64]

    const int tid  = threadIdx.x;
    const int lane = tid & 31, wid = tid >> 5;
    const int gid  = lane >> 2, tig = lane & 3;
    const int mw   = wid & 3,  nw  = wid >> 2;
    const int q0 = blockIdx.x * 64;
    const int h  = blockIdx.y, bb = blockIdx.z;
    const size_t bh = (size_t)(bb * NH_ + h);
    const float* Qg = g_Q + bh * S_ * H_;
    const float* Kg = g_K + bh * S_ * H_;
    const float* Vg = g_V + bh * S_ * H_;

    // fill Q tile once
#pragma unroll
    for (int t = 0; t < 8; t++) {
        int idx = tid + t * 256;
        int r = idx >> 5, sl = idx & 31;
        *reinterpret_cast<float4*>(&Qs[r * 132 + sl * 4]) =
            *reinterpret_cast<const float4*>(&Qg[(size_t)(q0 + r) * H_ + sl * 4]);
    }

    float O[8][4];
#pragma unroll
    for (int nt = 0; nt < 8; nt++)
#pragma unroll
        for (int j = 0; j < 4; j++) O[nt][j] = 0.0f;
    float m0 = -1e30f, m1 = -1e30f, l0 = 0.0f, l1 = 0.0f;
    const int r0 = mw * 16 + gid;

    for (int kt = 0; kt < 8; kt++) {
        __syncthreads();                 // prev iter done with Ks(=Ps)/Vs; Qs ready
        const int k0 = kt * 64;
#pragma unroll
        for (int t = 0; t < 8; t++) {
            int idx = tid + t * 256;
            int r = idx >> 5, sl = idx & 31;
            *reinterpret_cast<float4*>(&Ks[r * 132 + sl * 4]) =
                *reinterpret_cast<const float4*>(&Kg[(size_t)(k0 + r) * H_ + sl * 4]);
            *reinterpret_cast<float4*>(&Vs[r * 136 + sl * 4]) =
                *reinterpret_cast<const float4*>(&Vg[(size_t)(k0 + r) * H_ + sl * 4]);
        }
        __syncthreads();

        // ---- S = Q K^T (Q pre-scaled) ----
        float c[4][4];
#pragma unroll
        for (int nt = 0; nt < 4; nt++)
#pragma unroll
            for (int j = 0; j < 4; j++) c[nt][j] = 0.0f;
        {
            const unsigned* Qu = reinterpret_cast<const unsigned*>(Qs);
            const unsigned* Ku = reinterpret_cast<const unsigned*>(Ks);
#pragma unroll
            for (int s = 0; s < 16; s++) {
                unsigned a0 = Qu[r0 * 132 + 8 * s + tig];
                unsigned a1 = Qu[(r0 + 8) * 132 + 8 * s + tig];
                unsigned a2 = Qu[r0 * 132 + 8 * s + tig + 4];
                unsigned a3 = Qu[(r0 + 8) * 132 + 8 * s + tig + 4];
#pragma unroll
                for (int nt = 0; nt < 4; nt++) {
                    int kn = nw * 32 + nt * 8 + gid;
                    unsigned b0 = Ku[kn * 132 + 8 * s + tig];
                    unsigned b1 = Ku[kn * 132 + 8 * s + tig + 4];
                    mma_tf32(c[nt], a0, a1, a2, a3, b0, b1);
                }
            }
        }

        // ---- mask + row max (thread -> quad -> cross-warp) ----
        float mx0 = -1e30f, mx1 = -1e30f;
#pragma unroll
        for (int nt = 0; nt < 4; nt++) {
            int kc = k0 + nw * 32 + nt * 8 + 2 * tig;
            int2 mk0 = *reinterpret_cast<const int2*>(
                &mask[((size_t)bb * S_ + (q0 + r0)) * S_ + kc]);
            int2 mk1 = *reinterpret_cast<const int2*>(
                &mask[((size_t)bb * S_ + (q0 + r0 + 8)) * S_ + kc]);
            if (mk0.x == 0) c[nt][0] = NEG_INF_;
            if (mk0.y == 0) c[nt][1] = NEG_INF_;
            if (mk1.x == 0) c[nt][2] = NEG_INF_;
            if (mk1.y == 0) c[nt][3] = NEG_INF_;
            mx0 = fmaxf(mx0, fmaxf(c[nt][0], c[nt][1]));
            mx1 = fmaxf(mx1, fmaxf(c[nt][2], c[nt][3]));
        }
        mx0 = fmaxf(mx0, __shfl_xor_sync(0xffffffffu, mx0, 1));
        mx0 = fmaxf(mx0, __shfl_xor_sync(0xffffffffu, mx0, 2));
        mx1 = fmaxf(mx1, __shfl_xor_sync(0xffffffffu, mx1, 1));
        mx1 = fmaxf(mx1, __shfl_xor_sync(0xffffffffu, mx1, 2));
        if (tig == 0) {
            rmax[nw * 64 + r0]     = mx0;
            rmax[nw * 64 + r0 + 8] = mx1;
        }
        __syncthreads();                 // rmax ready; Ks reads done (Ps writes safe)

        float nm0 = fmaxf(m0, fmaxf(rmax[r0],     rmax[64 + r0]));
        float nm1 = fmaxf(m1, fmaxf(rmax[r0 + 8], rmax[64 + r0 + 8]));
        float al0 = __expf(m0 - nm0), al1 = __expf(m1 - nm1);
        m0 = nm0; m1 = nm1;

        float s0 = 0.0f, s1 = 0.0f;
#pragma unroll
        for (int nt = 0; nt < 4; nt++) {
            float p0 = __expf(c[nt][0] - nm0);
            float p1 = __expf(c[nt][1] - nm0);
            float p2 = __expf(c[nt][2] - nm1);
            float p3 = __expf(c[nt][3] - nm1);
            s0 += p0 + p1; s1 += p2 + p3;
            int col = nw * 32 + nt * 8 + 2 * tig;
            *reinterpret_cast<float2*>(&Ps[r0 * 68 + col]) =
                make_float2(tf32r(p0), tf32r(p1));
            *reinterpret_cast<float2*>(&Ps[(r0 + 8) * 68 + col]) =
                make_float2(tf32r(p2), tf32r(p3));
        }
        s0 += __shfl_xor_sync(0xffffffffu, s0, 1);
        s0 += __shfl_xor_sync(0xffffffffu, s0, 2);
        s1 += __shfl_xor_sync(0xffffffffu, s1, 1);
        s1 += __shfl_xor_sync(0xffffffffu, s1, 2);
        if (tig == 0) {
            rsum[nw * 64 + r0]     = s0;
            rsum[nw * 64 + r0 + 8] = s1;
        }
        // rescale O while waiting
#pragma unroll
        for (int nt = 0; nt < 8; nt++) {
            O[nt][0] *= al0; O[nt][1] *= al0;
            O[nt][2] *= al1; O[nt][3] *= al1;
        }
        __syncthreads();                 // Ps + rsum visible

        l0 = l0 * al0 + rsum[r0]     + rsum[64 + r0];
        l1 = l1 * al1 + rsum[r0 + 8] + rsum[64 + r0 + 8];

        // ---- O += P @ V ----
        {
            const unsigned* Pu = reinterpret_cast<const unsigned*>(Ps);
            const unsigned* Vu = reinterpret_cast<const unsigned*>(Vs);
#pragma unroll
            for (int ks = 0; ks < 8; ks++) {
                unsigned a0 = Pu[r0 * 68 + 8 * ks + tig];
                unsigned a1 = Pu[(r0 + 8) * 68 + 8 * ks + tig];
                unsigned a2 = Pu[r0 * 68 + 8 * ks + tig + 4];
                unsigned a3 = Pu[(r0 + 8) * 68 + 8 * ks + tig + 4];
#pragma unroll
                for (int nt = 0; nt < 8; nt++) {
                    int d = nw * 64 + nt * 8 + gid;
                    unsigned b0 = Vu[(8 * ks + tig) * 136 + d];
                    unsigned b1 = Vu[(8 * ks + tig + 4) * 136 + d];
                    mma_tf32(O[nt], a0, a1, a2, a3, b0, b1);
                }
            }
        }
    }

    // ---- normalize + write ctx (b, s, h*H+d) ----
    float inv0 = 1.0f / l0, inv1 = 1.0f / l1;
#pragma unroll
    for (int nt = 0; nt < 8; nt++) {
        int d = nw * 64 + nt * 8 + 2 * tig;
        *reinterpret_cast<float2*>(
            &g_ctx[((size_t)bb * S_ + (q0 + r0)) * NHH_ + h * H_ + d]) =
            make_float2(O[nt][0] * inv0, O[nt][1] * inv0);
        *reinterpret_cast<float2*>(
            &g_ctx[((size_t)bb * S_ + (q0 + r0 + 8)) * NHH_ + h * H_ + d]) =
            make_float2(O[nt][2] * inv1, O[nt][3] * inv1);
    }
}

// ---------------- swizzled float4 tiles for the fp32 out kernel --------------
__device__ __forceinline__ float4 ld4sw(const float* b, int row, int slot, int nsl) {
    int ph = slot ^ (row & (nsl - 1));
    return *reinterpret_cast<const float4*>(b + ((row * nsl + ph) << 2));
}
__device__ __forceinline__ void st4sw(float* b, int row, int slot, int nsl, float4 v) {
    int ph = slot ^ (row & (nsl - 1));
    *reinterpret_cast<float4*>(b + ((row * nsl + ph) << 2)) = v;
}

// =============================================================================
// Kernel 3: out = ctx @ Wo + enc, then LayerNorm(last dim).  (fp32 FFMA)
// =============================================================================
__global__ void __launch_bounds__(256) out_kernel(
    const float* __restrict__ enc, const float* __restrict__ Wo,
    const float* __restrict__ gamma, const float* __restrict__ beta,
    float* __restrict__ out)
{
    __shared__ float As[64 * 32];    // 64 m-rows x 8 slots (k)
    __shared__ float Bs[32 * 128];   // 32 k-rows x 32 slots (n)
    const int tid = threadIdx.x, tx = tid & 15, ty = tid >> 4;
    const int m0 = blockIdx.x * 64;

    float acc[4][8];
#pragma unroll
    for (int i = 0; i < 4; i++)
#pragma unroll
        for (int j = 0; j < 8; j++) acc[i][j] = 0.0f;

    for (int kc = 0; kc < NHH_; kc += 32) {
        if (kc) __syncthreads();
#pragma unroll
        for (int t = 0; t < 2; t++) {
            int idx = tid + t * 256;
            int r = idx >> 3, sl = idx & 7;
            st4sw(As, r, sl, 8,
                  *reinterpret_cast<const float4*>(&g_ctx[(size_t)(m0 + r) * NHH_ + kc + sl * 4]));
        }
#pragma unroll
        for (int t = 0; t < 4; t++) {
            int idx = tid + t * 256;
            int r = idx >> 5, sl = idx & 31;
            st4sw(Bs, r, sl, 32,
                  *reinterpret_cast<const float4*>(&Wo[(size_t)(kc + r) * H_ + sl * 4]));
        }
        __syncthreads();
#pragma unroll
        for (int s = 0; s < 8; s++) {
            float4 av[4];
#pragma unroll
            for (int i = 0; i < 4; i++) av[i] = ld4sw(As, 4 * ty + i, s, 8);
#pragma unroll
            for (int t = 0; t < 4; t++) {
                int k = 4 * s + t;
                float4 b1 = ld4sw(Bs, k, tx, 32);
                float4 b2 = ld4sw(Bs, k, tx + 16, 32);
#pragma unroll
                for (int i = 0; i < 4; i++) {
                    float a = reinterpret_cast<const float*>(&av[i])[t];
                    acc[i][0] += a * b1.x; acc[i][1] += a * b1.y;
                    acc[i][2] += a * b1.z; acc[i][3] += a * b1.w;
                    acc[i][4] += a * b2.x; acc[i][5] += a * b2.y;
                    acc[i][6] += a * b2.z; acc[i][7] += a * b2.w;
                }
            }
        }
    }

    float4 g1  = *reinterpret_cast<const float4*>(&gamma[4 * tx]);
    float4 g2  = *reinterpret_cast<const float4*>(&gamma[64 + 4 * tx]);
    float4 be1 = *reinterpret_cast<const float4*>(&beta[4 * tx]);
    float4 be2 = *reinterpret_cast<const float4*>(&beta[64 + 4 * tx]);

#pragma unroll
    for (int i = 0; i < 4; i++) {
        int m = m0 + 4 * ty + i;
        float4 e1 = *reinterpret_cast<const float4*>(&enc[(size_t)m * H_ + 4 * tx]);
        float4 e2 = *reinterpret_cast<const float4*>(&enc[(size_t)m * H_ + 64 + 4 * tx]);
        float x[8];
        x[0] = acc[i][0] + e1.x; x[1] = acc[i][1] + e1.y;
        x[2] = acc[i][2] + e1.z; x[3] = acc[i][3] + e1.w;
        x[4] = acc[i][4] + e2.x; x[5] = acc[i][5] + e2.y;
        x[6] = acc[i][6] + e2.z; x[7] = acc[i][7] + e2.w;

        float sm_ = 0.0f, sq = 0.0f;
#pragma unroll
        for (int j = 0; j < 8; j++) { sm_ += x[j]; sq += x[j] * x[j]; }
#pragma unroll
        for (int o = 8; o > 0; o >>= 1) {
            sm_ += __shfl_xor_sync(0xffffffffu, sm_, o);
            sq  += __shfl_xor_sync(0xffffffffu, sq,  o);
        }
        float mean = sm_ * (1.0f / 128.0f);
        float var  = sq * (1.0f / 128.0f) - mean * mean;
        float rstd = rsqrtf(var + 1e-6f);

        float4 y1 = make_float4((x[0] - mean) * rstd * g1.x + be1.x,
                                (x[1] - mean) * rstd * g1.y + be1.y,
                                (x[2] - mean) * rstd * g1.z + be1.z,
                                (x[3] - mean) * rstd * g1.w + be1.w);
        float4 y2 = make_float4((x[4] - mean) * rstd * g2.x + be2.x,
                                (x[5] - mean) * rstd * g2.y + be2.y,
                                (x[6] - mean) * rstd * g2.z + be2.z,
                                (x[7] - mean) * rstd * g2.w + be2.w);
        *reinterpret_cast<float4*>(&out[(size_t)m * H_ + 4 * tx]) = y1;
        *reinterpret_cast<float4*>(&out[(size_t)m * H_ + 64 + 4 * tx]) = y2;
    }
}

// =============================================================================
extern "C" void kernel_launch(void* const* d_in, const int* in_sizes, int n_in,
                              void* d_out, int out_size)
{
    const float* enc   = (const float*)d_in[0];
    const int*   mask  = (const int*)  d_in[1];
    const float* Wq    = (const float*)d_in[2];
    const float* Wk    = (const float*)d_in[3];
    const float* Wv    = (const float*)d_in[4];
    const float* Wo    = (const float*)d_in[5];
    const float* gamma = (const float*)d_in[6];
    const float* beta  = (const float*)d_in[7];
    float* out = (float*)d_out;

    const int smem1 = (64 * 132 + 128 * 72) * (int)sizeof(float);   // 70656 B
    cudaFuncSetAttribute(qkv_kernel, cudaFuncAttributeMaxDynamicSharedMemorySize, smem1);
    dim3 g1(NHH_ / 64, (B_ * S_) / 64, 3);
    qkv_kernel<<<g1, 256, smem1>>>(enc, Wq, Wk, Wv);

    const int smem2 = (64 * 132 + 64 * 132 + 64 * 136 + 256) * (int)sizeof(float); // 103424 B
    cudaFuncSetAttribute(attn_kernel, cudaFuncAttributeMaxDynamicSharedMemorySize, smem2);
    dim3 g2(S_ / 64, NH_, B_);
    attn_kernel<<<g2, 256, smem2>>>(mask);

    out_kernel<<<(B_ * S_) / 64, 256>>>(enc, Wo, gamma, beta, out);
}